// round 15
// baseline (speedup 1.0000x reference)
#include <cuda_runtime.h>
#include <cuda_fp16.h>
#include <math.h>
#include <float.h>
#include <stdint.h>

#define NB 8
#define NT 2048
#define NC 2048
#define NE 32
#define NH 64
#define HC (NH*NC)
#define NROWS (NB*NT)

// ---------------- scratch (device globals; no allocation allowed) ----------------
__device__ __align__(16) float g_part[NB*16*NC];
__device__ float g_dots[NE + NB + NB*NE];
__device__ __align__(16) __half g_xh[(size_t)NROWS*NC];    // fp16 X (b,t,c) 64MiB
__device__ __align__(16) __half g_wvhi[NB*HC];             // Wv_eff fp16 (b,h,c)
__device__ __align__(16) float  g_wo[NB*HC];               // Wo_eff fp32 (b,h,c)
__device__ __align__(16) __half g_wothi[NB*HC];            // Wo_eff^T fp16 (b,d,h)
__device__ __align__(16) __half g_chi[(size_t)NROWS*NH];   // comb fp16 (row,h)

// ---------------- helpers ----------------
__device__ __forceinline__ uint32_t smem_u32(const void* p){
    uint32_t a;
    asm("{ .reg .u64 t; cvta.to.shared.u64 t, %1; cvt.u32.u64 %0, t; }" : "=r"(a) : "l"(p));
    return a;
}
#define SWZ(x) ((x) ^ (((x)>>3)&0x70))
#define CPA16(dst,src) asm volatile("cp.async.cg.shared.global [%0], [%1], 16;" :: "r"(dst), "l"(src))
#define CPC() asm volatile("cp.async.commit_group;")
#define CPW1() asm volatile("cp.async.wait_group 1;")
#define CPW0() asm volatile("cp.async.wait_group 0;")

__device__ __forceinline__ void ldsm_x4(uint32_t a, uint32_t& r0, uint32_t& r1, uint32_t& r2, uint32_t& r3){
    asm volatile("ldmatrix.sync.aligned.m8n8.x4.shared.b16 {%0,%1,%2,%3}, [%4];"
        : "=r"(r0),"=r"(r1),"=r"(r2),"=r"(r3) : "r"(a));
}
__device__ __forceinline__ void mma_f16(float* c, uint32_t a0,uint32_t a1,uint32_t a2,uint32_t a3,
                                        uint32_t b0,uint32_t b1){
    asm volatile("mma.sync.aligned.m16n8k16.row.col.f32.f16.f16.f32 "
        "{%0,%1,%2,%3}, {%4,%5,%6,%7}, {%8,%9}, {%0,%1,%2,%3};"
        : "+f"(c[0]),"+f"(c[1]),"+f"(c[2]),"+f"(c[3])
        : "r"(a0),"r"(a1),"r"(a2),"r"(a3),"r"(b0),"r"(b1));
}
__device__ __forceinline__ float wredsum(float v){
    #pragma unroll
    for (int o=16;o>0;o>>=1) v += __shfl_xor_sync(0xffffffffu, v, o);
    return v;
}
__device__ __forceinline__ float wredmax(float v){
    #pragma unroll
    for (int o=16;o>0;o>>=1) v = fmaxf(v, __shfl_xor_sync(0xffffffffu, v, o));
    return v;
}
// pack fp32 pair into fp16x2
__device__ __forceinline__ uint32_t pack2h(float2 f){
    __half2 h2 = __floats2half2_rn(f.x, f.y);
    return *reinterpret_cast<uint32_t*>(&h2);
}

// ---------------- 1) mean pass: column sums + fp16 X ----------------
__global__ void k_mean(const float* __restrict__ X){
    int c = blockIdx.x*256 + threadIdx.x;
    int s = blockIdx.y, b = blockIdx.z;
    size_t base = ((size_t)b*NT + (size_t)s*128)*NC + c;
    const float* p = X + base;
    __half* ph = g_xh + base;
    float acc = 0.f;
    #pragma unroll 4
    for (int t=0;t<128;t++){
        float f = p[(size_t)t*NC];
        acc += f;
        ph[(size_t)t*NC] = __float2half_rn(f);
    }
    g_part[(b*16+s)*NC + c] = acc;
}

// ---------------- 2) norms + affinity dots ----------------
__global__ void k_dots(const float* __restrict__ sim){
    __shared__ float sred[4];
    int task = blockIdx.x;
    int tid = threadIdx.x;
    float acc = 0.f;
    if (task < NE){
        int e = task;
        for (int c = tid; c < NC; c += 128){ float v = sim[c*NE + e]; acc += v*v; }
    } else if (task < NE+NB){
        int b = task - NE;
        for (int c = tid; c < NC; c += 128){
            float v = 0.f;
            #pragma unroll
            for (int s=0;s<16;s++) v += g_part[(b*16+s)*NC + c];
            acc += v*v;
        }
    } else {
        int p = task - NE - NB;
        int b = p >> 5, e = p & 31;
        for (int c = tid; c < NC; c += 128){
            float v = 0.f;
            #pragma unroll
            for (int s=0;s<16;s++) v += g_part[(b*16+s)*NC + c];
            acc += v * sim[c*NE + e];
        }
    }
    acc = wredsum(acc);
    if ((tid & 31) == 0) sred[tid>>5] = acc;
    __syncthreads();
    if (tid == 0) g_dots[task] = (sred[0]+sred[1])+(sred[2]+sred[3]);
}

// ---------------- 3) gating + fold; Wv to fp16, Wo kept fp32 ----------------
__global__ void k_weff(const float* __restrict__ gates,
                       const float* __restrict__ w_v, const float* __restrict__ o_w){
    __shared__ float r[NB*NE];
    int tid = threadIdx.x;
    {
        int lane = tid & 31, b = tid >> 5;
        float nsim2 = g_dots[lane];
        float nseq2 = g_dots[NE + b];
        float dot   = g_dots[NE + NB + b*NE + lane];
        float aff = dot / sqrtf(nsim2 * nseq2);
        float sig = 1.f / (1.f + expf(-gates[lane]));
        float logit = aff - sig;
        float gated = fmaxf(logit, 0.f);
        bool  act = gated > 0.f;
        unsigned actm = __ballot_sync(0xffffffffu, act);
        bool use = act;
        if (actm == 0u){
            int rank = 0;
            #pragma unroll
            for (int e=0;e<NE;e++){
                float le = __shfl_sync(0xffffffffu, logit, e);
                rank += (le > logit) || (le == logit && e < lane);
            }
            use = rank < 16;
        }
        float v = use ? gated : -FLT_MAX;
        float mx = wredmax(v);
        float ex = use ? expf(gated - mx) : 0.f;
        float sm = wredsum(ex);
        r[tid] = ex / sm;
    }
    __syncthreads();
    int j = blockIdx.x*256 + tid;
    float accv[NB], acco[NB];
    #pragma unroll
    for (int b=0;b<NB;b++){ accv[b]=0.f; acco[b]=0.f; }
    for (int e=0;e<NE;e++){
        float wv = w_v[(size_t)e*HC + j];
        float wo = o_w[(size_t)e*HC + j];
        #pragma unroll
        for (int b=0;b<NB;b++){
            float rr = r[b*NE+e];
            accv[b] = fmaf(rr, wv, accv[b]);
            acco[b] = fmaf(rr, wo, acco[b]);
        }
    }
    #pragma unroll
    for (int b=0;b<NB;b++){
        g_wvhi[(size_t)b*HC + j] = __float2half_rn(accv[b]);
        g_wo[(size_t)b*HC + j] = acco[b];
    }
}

// ---------------- 3b) transpose Wo_eff (b,h,d) -> (b,d,h) fp16 ----------------
__global__ void k_trans2(){
    __shared__ float ts[64][65];
    int b = blockIdx.y, d0 = blockIdx.x*64;
    int tid = threadIdx.x;
    int cc = tid & 63, q = tid >> 6;
    #pragma unroll
    for (int i=0;i<16;i++){
        int h = i*4 + q;
        ts[h][cc] = g_wo[(size_t)b*HC + (size_t)h*NC + d0 + cc];
    }
    __syncthreads();
    #pragma unroll
    for (int i=0;i<16;i++){
        int d = i*4 + q;
        g_wothi[(size_t)b*HC + (size_t)(d0+d)*NH + cc] = __float2half_rn(ts[cc][d]);
    }
}

// ---------------- GEMM1 smem: 3 stages x 16KB (A fp16 8KB + B fp16 8KB) ----------------
#define G1_A     0
#define G1_B_HI  8192
#define G1_STG   16384
#define G1_SMEM  (3*G1_STG)

__device__ __forceinline__ void g1_load(uint32_t stg, const __half* xh,
        const __half* bh, int ck, int tid){
    int c0 = ck*64;
    // A: 64 rows x 64 fp16 = 512 granules
    #pragma unroll
    for (int i=0;i<2;i++){
        int u = tid + i*256;
        int row = u>>3, seg = u&7;
        uint32_t dst = stg + G1_A + SWZ(row*128 + seg*16);
        CPA16(dst, xh + (size_t)row*NC + c0 + seg*8);
    }
    // B: 64n x 64k fp16 = 512 granules
    #pragma unroll
    for (int i=0;i<2;i++){
        int u = tid + i*256;
        int n = u>>3, seg = u&7;
        uint32_t dst = stg + G1_B_HI + SWZ(n*128 + seg*16);
        CPA16(dst, bh + (size_t)n*NC + c0 + seg*8);
    }
    CPC();
}

// ---------------- 4) GEMM1: comb = Xh @ Wv_hi^T (pure ldsm+HMMA) ----------------
// block tile 64m x 64n, 256 threads, warp grid 4m x 2n, warp tile 16m x 32n
__global__ void __launch_bounds__(256, 3) k_gemm1_tc(){
    extern __shared__ __align__(1024) char sm1[];
    uint32_t sb = smem_u32(sm1);
    int tid = threadIdx.x;
    int wid = tid >> 5, lid = tid & 31;
    int wm = wid & 3, wn = wid >> 2;
    int mt0 = blockIdx.x, b = blockIdx.y;
    int t0 = mt0*64;

    const __half* xh = g_xh + ((size_t)(b*NT + t0))*NC;
    const __half* bh = g_wvhi + (size_t)b*HC;

    float acc[4][4];
    #pragma unroll
    for (int nt=0;nt<4;nt++)
        #pragma unroll
        for (int q=0;q<4;q++) acc[nt][q] = 0.f;

    g1_load(sb + 0*G1_STG, xh, bh, 0, tid);
    g1_load(sb + 1*G1_STG, xh, bh, 1, tid);

    for (int t=0;t<32;t++){
        if (t < 31) { CPW1(); } else { CPW0(); }
        __syncthreads();
        if (t+2 < 32) g1_load(sb + ((t+2)%3)*G1_STG, xh, bh, t+2, tid);
        uint32_t stg = sb + (t%3)*G1_STG;
        #pragma unroll
        for (int kk=0;kk<4;kk++){
            uint32_t ahf[4];
            {
                int row = wm*16 + (lid&15);
                uint32_t off = SWZ(row*128 + kk*32 + (lid>>4)*16);
                ldsm_x4(stg + G1_A + off, ahf[0],ahf[1],ahf[2],ahf[3]);
            }
            uint32_t bhf[4][2];
            #pragma unroll
            for (int ng=0;ng<2;ng++){
                int row = wn*32 + ng*16 + (lid&7) + ((lid>>4)<<3);
                uint32_t off = SWZ(row*128 + kk*32 + ((lid>>3)&1)*16);
                ldsm_x4(stg + G1_B_HI + off, bhf[2*ng][0], bhf[2*ng][1], bhf[2*ng+1][0], bhf[2*ng+1][1]);
            }
            #pragma unroll
            for (int nt=0;nt<4;nt++){
                mma_f16(acc[nt], ahf[0],ahf[1],ahf[2],ahf[3], bhf[nt][0],bhf[nt][1]);
            }
        }
    }

    // epilogue: comb -> fp16
    #pragma unroll
    for (int nt=0;nt<4;nt++){
        float* c = acc[nt];
        int row = b*NT + t0 + wm*16 + (lid>>2);
        int col = wn*32 + nt*8 + (lid&3)*2;
        #pragma unroll
        for (int h2=0;h2<2;h2++){
            int rr = row + h2*8;
            *(uint32_t*)(g_chi + (size_t)rr*NH + col) = pack2h(make_float2(c[2*h2], c[2*h2+1]));
        }
    }
}

// ---------------- GEMM2 smem layout: 32KB single shot ----------------
#define G2_A_HI  0
#define G2_B_HI  16384
#define G2_SMEM  32768

// ---------------- 5) GEMM2: out = comb @ Wo_hi (HMMA) ----------------
__global__ void __launch_bounds__(256, 2) k_gemm2_tc(float* __restrict__ out){
    extern __shared__ __align__(1024) char sm2[];
    uint32_t sb = smem_u32(sm2);
    int tid = threadIdx.x;
    int wid = tid >> 5, lid = tid & 31;
    int wm = wid & 3, wn = wid >> 2;            // warp tile 32m x 64n
    int nt0 = blockIdx.x, mt0 = blockIdx.y;
    int mbase = mt0*128;
    int b = mbase / NT;
    int d0 = nt0*128;

    const __half* ah = g_chi + (size_t)mbase*NH;
    const __half* bh = g_wothi + (size_t)b*HC + (size_t)d0*NH;

    #pragma unroll
    for (int i=0;i<8;i++){
        int u = tid + i*256;
        int sel = u>>10, w = u & 1023;
        int row = w>>3, seg = w&7;
        uint32_t off = SWZ(row*128 + seg*16);
        const __half* src = (sel==0?ah:bh) + (size_t)row*NH + seg*8;
        uint32_t base = (sel==0?G2_A_HI:G2_B_HI);
        CPA16(sb + base + off, src);
    }
    CPC();
    CPW0();
    __syncthreads();

    float acc[2][8][4];
    #pragma unroll
    for (int mt=0;mt<2;mt++)
        #pragma unroll
        for (int nt=0;nt<8;nt++)
            #pragma unroll
            for (int q=0;q<4;q++) acc[mt][nt][q] = 0.f;

    #pragma unroll
    for (int kk=0;kk<4;kk++){
        uint32_t ahf[2][4], bhf[8][2];
        #pragma unroll
        for (int mt=0;mt<2;mt++){
            int row = wm*32 + mt*16 + (lid&15);
            uint32_t off = SWZ(row*128 + kk*32 + (lid>>4)*16);
            ldsm_x4(sb + G2_A_HI + off, ahf[mt][0],ahf[mt][1],ahf[mt][2],ahf[mt][3]);
        }
        #pragma unroll
        for (int ng=0;ng<4;ng++){
            int row = wn*64 + ng*16 + (lid&7) + ((lid>>4)<<3);
            uint32_t off = SWZ(row*128 + kk*32 + ((lid>>3)&1)*16);
            ldsm_x4(sb + G2_B_HI + off, bhf[2*ng][0], bhf[2*ng][1], bhf[2*ng+1][0], bhf[2*ng+1][1]);
        }
        #pragma unroll
        for (int mt=0;mt<2;mt++){
            #pragma unroll
            for (int nt=0;nt<8;nt++){
                mma_f16(acc[mt][nt], ahf[mt][0],ahf[mt][1],ahf[mt][2],ahf[mt][3], bhf[nt][0],bhf[nt][1]);
            }
        }
    }

    #pragma unroll
    for (int mt=0;mt<2;mt++){
        #pragma unroll
        for (int nt=0;nt<8;nt++){
            float* c = acc[mt][nt];
            int row = mbase + wm*32 + mt*16 + (lid>>2);
            int col = d0 + wn*64 + nt*8 + (lid&3)*2;
            *(float2*)(out + (size_t)row*NC + col)       = make_float2(c[0], c[1]);
            *(float2*)(out + (size_t)(row+8)*NC + col)   = make_float2(c[2], c[3]);
        }
    }
}

// ---------------- launch ----------------
extern "C" void kernel_launch(void* const* d_in, const int* in_sizes, int n_in,
                              void* d_out, int out_size){
    const float* X     = (const float*)d_in[0];
    const float* sim   = (const float*)d_in[1];
    const float* gates = (const float*)d_in[2];
    const float* w_v   = (const float*)d_in[5];
    const float* o_w   = (const float*)d_in[6];
    float* out = (float*)d_out;

    static int attr_done = 0;
    if (!attr_done){
        cudaFuncSetAttribute(k_gemm1_tc, cudaFuncAttributeMaxDynamicSharedMemorySize, G1_SMEM);
        cudaFuncSetAttribute(k_gemm2_tc, cudaFuncAttributeMaxDynamicSharedMemorySize, G2_SMEM);
        attr_done = 1;
    }

    k_mean     <<<dim3(NC/256, 16, NB), 256>>>(X);
    k_dots     <<<NE + NB + NB*NE, 128>>>(sim);
    k_weff     <<<HC/256, 256>>>(gates, w_v, o_w);
    k_trans2   <<<dim3(NC/64, NB), 256>>>();
    k_gemm1_tc <<<dim3(NT/64, NB), 256, G1_SMEM>>>();
    k_gemm2_tc <<<dim3(NC/128, NROWS/128), 256, G2_SMEM>>>(out);
    (void)in_sizes; (void)n_in; (void)out_size;
}